// round 15
// baseline (speedup 1.0000x reference)
#include <cuda_runtime.h>
#include <math.h>

// Problem constants
#define BB 64
#define NN 8732
#define CC 21
#define KCAND 200
#define MAXPC 20
#define MAXTOT 20
#define FULLM 0xffffffffu

#define TH_C  0.96f             // collect threshold, classes >= 1 (proven)
#define TH_0  0.92f             // collect threshold, class 0      (proven)

#define DB  256                           // decode block size
#define BPB ((NN + DB - 1) / DB)          // 35 decode blocks per batch
#define NW  ((NN + 31) / 32)              // 273 mask words per (b,c)
#define PD  8                             // prefetched boxes per sorted run
#define WPB 4                             // nms: warps (classes) per block

// Scratch (static device globals: allowed; no runtime allocation)
__device__ float4        g_boxes[BB * NN];                 // decoded boxes
__device__ unsigned char g_mask[BB * NN];                  // argmax != 0 (fallback)
__device__ unsigned      g_cmask[(size_t)BB * CC * NW];    // candidate bitmask
__device__ float         g_cls_scores[BB * CC * MAXPC];    // sorted desc
__device__ float4        g_cls_boxes[BB * CC * MAXPC];

// ---------------------------------------------------------------------------
// Kernel A (measured 16.6us, unchanged): one thread per (b,n); registers;
// emits decoded box, argmax mask byte, 21 candidate ballots per warp.
// ---------------------------------------------------------------------------
__global__ __launch_bounds__(DB) void decode_kernel(
        const float* __restrict__ deltas,
        const float* __restrict__ labels,
        const float* __restrict__ anchors) {
    const int bx   = blockIdx.x;
    const int b    = bx / BPB;
    const int blk  = bx % BPB;
    const int n    = blk * DB + threadIdx.x;
    const int lane = threadIdx.x & 31;
    const bool valid = (n < NN);

    float sc[CC];
    bool  masked = false;

    if (valid) {
        const float* lr = labels + ((size_t)b * NN + n) * CC;
#pragma unroll
        for (int c = 0; c < CC; c++) sc[c] = __ldg(lr + c);

        float best = sc[0];
        int   bi   = 0;
#pragma unroll
        for (int c = 1; c < CC; c++) {
            if (sc[c] > best) { best = sc[c]; bi = c; }
        }
        masked = (bi != 0);
        g_mask[(size_t)b * NN + n] = masked ? 1 : 0;

        float4 a = __ldg(((const float4*)anchors) + n);
        float4 d = __ldg(((const float4*)deltas) + (size_t)b * NN + n);
        d.x *= 0.1f; d.y *= 0.1f; d.z *= 0.2f; d.w *= 0.2f;

        float ah  = a.z - a.x;
        float aw  = a.w - a.y;
        float acy = a.x + 0.5f * ah;
        float acx = a.y + 0.5f * aw;
        float cy  = d.x * ah + acy;
        float cx  = d.y * aw + acx;
        float h   = expf(d.z) * ah;
        float w   = expf(d.w) * aw;

        g_boxes[(size_t)b * NN + n] = make_float4(cy - 0.5f * h, cx - 0.5f * w,
                                                  cy + 0.5f * h, cx + 0.5f * w);
    }

    const int  w      = n >> 5;
    const bool wvalid = (blk * DB + (threadIdx.x & ~31)) < NN;
#pragma unroll
    for (int c = 0; c < CC; c++) {
        const float th  = (c == 0) ? TH_0 : TH_C;
        bool pred = valid && masked && (sc[c] >= th);
        unsigned bal = __ballot_sync(FULLM, pred);
        if (lane == 0 && wvalid)
            g_cmask[(size_t)(b * CC + c) * NW + w] = bal;
    }
}

// ---------------------------------------------------------------------------
// IoU, exactly mirroring the reference fp32 formula
// ---------------------------------------------------------------------------
__device__ __forceinline__ float iou_f(float4 A, float4 B2) {
    float areaA = (A.z - A.x) * (A.w - A.y);
    float areaB = (B2.z - B2.x) * (B2.w - B2.y);
    float ih = fminf(A.z, B2.z) - fmaxf(A.x, B2.x); ih = fmaxf(ih, 0.0f);
    float iw = fminf(A.w, B2.w) - fmaxf(A.y, B2.y); iw = fmaxf(iw, 0.0f);
    float inter = ih * iw;
    return inter / (areaA + areaB - inter + 1e-8f);
}

// key pack: [score bits:32 | (16383-n):14 | 0:9] — desc => score desc, n asc
__device__ __forceinline__ unsigned long long pack_key(float s, unsigned n) {
    return ((unsigned long long)__float_as_uint(s) << 32)
         | ((unsigned long long)((16383u - n) & 0x3FFFu) << 9);
}

// Warp-register bitonic sort of 32 u64 keys, descending; no barriers.
__device__ __forceinline__ unsigned long long warpsort32_desc(
        unsigned long long key, int lane) {
#pragma unroll
    for (int k = 2; k <= 32; k <<= 1) {
#pragma unroll
        for (int j = k >> 1; j >= 1; j >>= 1) {
            unsigned long long other = __shfl_xor_sync(FULLM, key, j);
            bool dd   = ((lane & k) == 0);
            bool low  = ((lane & j) == 0);
            bool wmax = (dd == low);
            key = wmax ? (key > other ? key : other)
                       : (key < other ? key : other);
        }
    }
    return key;
}

// ---------------------------------------------------------------------------
// Kernel B: ONE WARP PER (b,c). Zero block barriers; 4 independent classes
// per 128-thread block. Per warp: bitmask collect (warp scan, batched gather)
// -> sequential register sorts of active runs -> lazy top-PD box prefetch ->
// REDUX-based merge-pop fused greedy NMS.
// ---------------------------------------------------------------------------
__global__ __launch_bounds__(32 * WPB) void nms_kernel(
        const float* __restrict__ labels) {
    const int wid  = threadIdx.x >> 5;
    const int lane = threadIdx.x & 31;
    const int bc   = blockIdx.x * WPB + wid;
    const int b    = bc / CC;
    const int c    = bc % CC;

    __shared__ unsigned long long sk[WPB][512];
    __shared__ float4             sbox[WPB][16 * PD];
    __shared__ int                scnt[WPB];

    unsigned long long* skw = sk[wid];
    float4*             sbw = sbox[wid];
    int*                hist = (int*)skw;         // fallback aliases own sk

    // ---- Collect: each lane owns 9 consecutive mask words
    const unsigned* Cm = g_cmask + (size_t)bc * NW;
    unsigned mw[9];
    int cnt_t = 0;
#pragma unroll
    for (int j = 0; j < 9; j++) {
        int widx = lane * 9 + j;
        mw[j] = (widx < NW) ? Cm[widx] : 0u;
        cnt_t += __popc(mw[j]);
    }
    int inc = cnt_t;                              // warp inclusive scan
#pragma unroll
    for (int off = 1; off < 32; off <<= 1) {
        int v = __shfl_up_sync(FULLM, inc, off);
        if (lane >= off) inc += v;
    }
    const int total = __shfl_sync(FULLM, inc, 31);
    int slot = inc - cnt_t;                       // exclusive prefix

    int cnt = total;
    if (cnt >= KCAND && cnt <= 512) {
        // Fast path: positions first (ALU), then batched loads, then stores
        int myn[16];
        int idx = 0;
#pragma unroll
        for (int j = 0; j < 9; j++) {
            unsigned m = mw[j];
            const int nb = (lane * 9 + j) * 32;
            while (m) {
                int bit = __ffs(m) - 1;
                m &= m - 1;
                int n = nb + bit;
                if (idx < 16) {
                    myn[idx] = n;
                } else {  // rare per-lane overflow: handle inline
                    float s = __ldg(labels + ((size_t)b * NN + n) * CC + c);
                    skw[slot + idx] = pack_key(s, (unsigned)n);
                }
                idx++;
            }
        }
        const int kk = min(idx, 16);
        float sv[16];
#pragma unroll
        for (int q = 0; q < 16; q++)
            if (q < kk)
                sv[q] = __ldg(labels + ((size_t)b * NN + myn[q]) * CC + c);
#pragma unroll
        for (int q = 0; q < 16; q++)
            if (q < kk)
                skw[slot + q] = pack_key(sv[q], (unsigned)myn[q]);
    } else {
        // Exact fallback (statistically never taken): single-warp histogram
        for (int i = lane; i < 1024; i += 32) hist[i] = 0;
        if (lane == 0) scnt[wid] = 0;
        __syncwarp();

        const float*         Lcol = labels + (size_t)b * NN * CC + c;
        const unsigned char* Mb   = g_mask + (size_t)b * NN;

        for (int n = lane; n < NN; n += 32) {
            if (Mb[n]) {
                float s = Lcol[(size_t)n * CC];
                if (s > 0.0f)
                    atomicAdd(&hist[min((int)(s * 1024.0f), 1023)], 1);
            }
        }
        __syncwarp();
        int cut = 0;
        if (lane == 0) {
            int cum = 0;
            for (int bin = 1023; bin >= 0; bin--) {
                cum += hist[bin];
                if (cum >= KCAND) { cut = bin; break; }
            }
        }
        cut = __shfl_sync(FULLM, cut, 0);
        __syncwarp();
        for (int n = lane; n < NN; n += 32) {
            if (Mb[n]) {
                float s = Lcol[(size_t)n * CC];
                if (s > 0.0f && min((int)(s * 1024.0f), 1023) >= cut) {
                    int p = atomicAdd(&scnt[wid], 1);
                    if (p < 512)
                        skw[p] = pack_key(s, (unsigned)n);
                }
            }
        }
        __syncwarp();
        cnt = scnt[wid];
    }
    __syncwarp();

    const int mn    = min(cnt, 512);
    const int nruns = (mn + 31) >> 5;
    for (int i = mn + lane; i < nruns * 32; i += 32) skw[i] = 0ULL;
    __syncwarp();

    // Sequential register sorts of the active runs (one warp, no barriers)
    for (int r = 0; r < nruns; r++) {
        unsigned long long k = skw[r * 32 + lane];
        k = warpsort32_desc(k, lane);
        skw[r * 32 + lane] = k;
    }
    __syncwarp();

    // Lazy prefetch: only the top PD boxes of each active run
    for (int i = lane; i < nruns * PD; i += 32) {
        const int run = i / PD;
        const int d   = i - run * PD;
        unsigned long long k = skw[run * 32 + d];
        if (k) {
            unsigned n = 16383u - (unsigned)((k >> 9) & 0x3FFFu);
            sbw[i] = g_boxes[(size_t)b * NN + n];
        }
    }
    __syncwarp();

    // Merge-pop fused with greedy NMS (whole warp; exact top-200 order)
    const int outbase = bc * MAXPC;
    int    head   = 0;
    int    kc     = 0;
    int    pops   = 0;
    const int maxpops = min(mn, KCAND);
    float4 mykept = make_float4(0.f, 0.f, 0.f, 0.f);

    while (pops < maxpops && kc < MAXPC) {
        unsigned long long hk = 0ULL;
        if (lane < nruns && head < 32) hk = skw[lane * 32 + head];
        // two-stage REDUX argmax (keys unique; 0 = exhausted)
        unsigned hi  = (unsigned)(hk >> 32);
        unsigned mhi = __reduce_max_sync(FULLM, hi);
        unsigned lo  = (hi == mhi) ? (unsigned)hk : 0u;
        unsigned mlo = __reduce_max_sync(FULLM, lo);
        unsigned long long bk = ((unsigned long long)mhi << 32) | mlo;
        if (bk == 0ULL) break;
        unsigned bal = __ballot_sync(FULLM, hk == bk);
        int bl = __ffs(bal) - 1;
        int hd = __shfl_sync(FULLM, head, bl);
        if (lane == bl) head++;
        pops++;

        float s = __uint_as_float(mhi);
        if (s <= 0.5f) break;                   // sorted: all later smaller
        float4 cb;
        if (hd < PD) {
            cb = sbw[bl * PD + hd];             // smem broadcast (common)
        } else {                                // rare: direct L1/L2 broadcast
            unsigned n = 16383u - (unsigned)((bk >> 9) & 0x3FFFu);
            cb = g_boxes[(size_t)b * NN + n];
        }

        bool ov = (lane < kc) && (iou_f(mykept, cb) > 0.5f);
        if (!__ballot_sync(FULLM, ov)) {
            if (lane == kc) mykept = cb;
            if (lane == 0) {
                g_cls_scores[outbase + kc] = s;
                g_cls_boxes[outbase + kc]  = cb;
            }
            kc++;
        }
    }
    if (lane < MAXPC && lane >= kc) {
        g_cls_scores[outbase + lane] = 0.0f;
        g_cls_boxes[outbase + lane]  = make_float4(0.f, 0.f, 0.f, 0.f);
    }
}

// ---------------------------------------------------------------------------
// Kernel C (proven): rank-based per-batch top-20 of 420 entries.
// ---------------------------------------------------------------------------
__global__ __launch_bounds__(448) void merge_kernel(float* __restrict__ out) {
    const int b   = blockIdx.x;
    const int tid = threadIdx.x;

    __shared__ unsigned long long ks[CC * MAXPC];   // 420 keys

    float s = 0.0f;
    if (tid < CC * MAXPC) {
        s = g_cls_scores[b * CC * MAXPC + tid];
        ks[tid] = ((unsigned long long)__float_as_uint(s) << 16)
                  | (unsigned long long)(1023 - tid);
    }
    __syncthreads();

    if (tid < CC * MAXPC) {
        const unsigned long long myk = ks[tid];
        int rank = 0;
#pragma unroll 4
        for (int j = 0; j < CC * MAXPC; j++)
            rank += (ks[j] > myk);

        if (rank < MAXTOT) {
            float4 bx  = make_float4(0.f, 0.f, 0.f, 0.f);
            float  lab = 0.0f;
            if (s > 0.0f) {
                bx = g_cls_boxes[b * CC * MAXPC + tid];
                bx.x = fminf(fmaxf(bx.x, 0.0f), 1.0f);
                bx.y = fminf(fmaxf(bx.y, 0.0f), 1.0f);
                bx.z = fminf(fmaxf(bx.z, 0.0f), 1.0f);
                bx.w = fminf(fmaxf(bx.w, 0.0f), 1.0f);
                lab = (float)(tid / MAXPC);
            }
            float* ob = out + (size_t)b * MAXTOT * 4;
            float* ov = out + (size_t)BB * MAXTOT * 4 + (size_t)b * MAXTOT;
            float* ol = out + (size_t)BB * MAXTOT * 4 + (size_t)BB * MAXTOT
                            + (size_t)b * MAXTOT;
            ob[rank * 4 + 0] = bx.x;
            ob[rank * 4 + 1] = bx.y;
            ob[rank * 4 + 2] = bx.z;
            ob[rank * 4 + 3] = bx.w;
            ov[rank] = s;
            ol[rank] = lab;
        }
    }
}

// ---------------------------------------------------------------------------
extern "C" void kernel_launch(void* const* d_in, const int* in_sizes, int n_in,
                              void* d_out, int out_size) {
    const float* deltas  = (const float*)d_in[0];  // (64, 8732, 4)
    const float* labels  = (const float*)d_in[1];  // (64, 8732, 21)
    const float* anchors = (const float*)d_in[2];  // (8732, 4)
    float* out = (float*)d_out;

    decode_kernel<<<BB * BPB, DB>>>(deltas, labels, anchors);
    nms_kernel<<<(BB * CC) / WPB, 32 * WPB>>>(labels);
    merge_kernel<<<BB, 448>>>(out);
}

// round 16
// speedup vs baseline: 1.1329x; 1.1329x over previous
#include <cuda_runtime.h>
#include <math.h>

// Problem constants
#define BB 64
#define NN 8732
#define CC 21
#define KCAND 200
#define MAXPC 20
#define MAXTOT 20
#define FULLM 0xffffffffu

#define TH_C  0.96f             // collect threshold, classes >= 1 (proven)
#define TH_0  0.92f             // collect threshold, class 0      (proven)

#define DB  256                           // decode block size
#define BPB ((NN + DB - 1) / DB)          // 35 decode blocks per batch
#define NW  ((NN + 31) / 32)              // 273 mask words per (b,c)
#define PD  8                             // prefetched boxes per sorted run
#define PITCH 33                          // padded run pitch (bank-conflict free)
#define PAD(s) ((((s) >> 5) * PITCH) + ((s) & 31))

// Scratch (static device globals: allowed; no runtime allocation)
__device__ float4        g_boxes[BB * NN];                 // decoded boxes
__device__ unsigned char g_mask[BB * NN];                  // argmax != 0 (fallback)
__device__ unsigned      g_cmask[(size_t)BB * CC * NW];    // candidate bitmask
__device__ float         g_cls_scores[BB * CC * MAXPC];    // sorted desc
__device__ float4        g_cls_boxes[BB * CC * MAXPC];

// ---------------------------------------------------------------------------
// Kernel A (R14-measured 16.6us + occupancy hint): one thread per (b,n).
// ---------------------------------------------------------------------------
__global__ __launch_bounds__(DB, 6) void decode_kernel(
        const float* __restrict__ deltas,
        const float* __restrict__ labels,
        const float* __restrict__ anchors) {
    const int bx   = blockIdx.x;
    const int b    = bx / BPB;
    const int blk  = bx % BPB;
    const int n    = blk * DB + threadIdx.x;
    const int lane = threadIdx.x & 31;
    const bool valid = (n < NN);

    float sc[CC];
    bool  masked = false;

    if (valid) {
        const float* lr = labels + ((size_t)b * NN + n) * CC;
#pragma unroll
        for (int c = 0; c < CC; c++) sc[c] = __ldg(lr + c);

        float best = sc[0];
        int   bi   = 0;
#pragma unroll
        for (int c = 1; c < CC; c++) {
            if (sc[c] > best) { best = sc[c]; bi = c; }
        }
        masked = (bi != 0);
        g_mask[(size_t)b * NN + n] = masked ? 1 : 0;

        float4 a = __ldg(((const float4*)anchors) + n);
        float4 d = __ldg(((const float4*)deltas) + (size_t)b * NN + n);
        d.x *= 0.1f; d.y *= 0.1f; d.z *= 0.2f; d.w *= 0.2f;

        float ah  = a.z - a.x;
        float aw  = a.w - a.y;
        float acy = a.x + 0.5f * ah;
        float acx = a.y + 0.5f * aw;
        float cy  = d.x * ah + acy;
        float cx  = d.y * aw + acx;
        float h   = expf(d.z) * ah;
        float w   = expf(d.w) * aw;

        g_boxes[(size_t)b * NN + n] = make_float4(cy - 0.5f * h, cx - 0.5f * w,
                                                  cy + 0.5f * h, cx + 0.5f * w);
    }

    const int  w      = n >> 5;
    const bool wvalid = (blk * DB + (threadIdx.x & ~31)) < NN;
#pragma unroll
    for (int c = 0; c < CC; c++) {
        const float th  = (c == 0) ? TH_0 : TH_C;
        bool pred = valid && masked && (sc[c] >= th);
        unsigned bal = __ballot_sync(FULLM, pred);
        if (lane == 0 && wvalid)
            g_cmask[(size_t)(b * CC + c) * NW + w] = bal;
    }
}

// ---------------------------------------------------------------------------
// IoU, exactly mirroring the reference fp32 formula
// ---------------------------------------------------------------------------
__device__ __forceinline__ float iou_f(float4 A, float4 B2) {
    float areaA = (A.z - A.x) * (A.w - A.y);
    float areaB = (B2.z - B2.x) * (B2.w - B2.y);
    float ih = fminf(A.z, B2.z) - fmaxf(A.x, B2.x); ih = fmaxf(ih, 0.0f);
    float iw = fminf(A.w, B2.w) - fmaxf(A.y, B2.y); iw = fmaxf(iw, 0.0f);
    float inter = ih * iw;
    return inter / (areaA + areaB - inter + 1e-8f);
}

// key pack: [score bits:32 | (16383-n):14 | 0:9] — desc => score desc, n asc
__device__ __forceinline__ unsigned long long pack_key(float s, unsigned n) {
    return ((unsigned long long)__float_as_uint(s) << 32)
         | ((unsigned long long)((16383u - n) & 0x3FFFu) << 9);
}

// Warp-register bitonic sort of 32 u64 keys, descending; no barriers.
__device__ __forceinline__ unsigned long long warpsort32_desc(
        unsigned long long key, int lane) {
#pragma unroll
    for (int k = 2; k <= 32; k <<= 1) {
#pragma unroll
        for (int j = k >> 1; j >= 1; j >>= 1) {
            unsigned long long other = __shfl_xor_sync(FULLM, key, j);
            bool dd   = ((lane & k) == 0);
            bool low  = ((lane & j) == 0);
            bool wmax = (dd == low);
            key = wmax ? (key > other ? key : other)
                       : (key < other ? key : other);
        }
    }
    return key;
}

// ---------------------------------------------------------------------------
// Kernel B (R14 structure): per-(b,c) block of 128 threads.
// Changes vs R14: padded run pitch (conflict-free pop heads) and prefetch
// fused into the sort (top-PD keys are already in lanes 0..PD-1's registers).
// ---------------------------------------------------------------------------
__global__ __launch_bounds__(128, 10) void nms_kernel(
        const float* __restrict__ labels) {
    const int bc   = blockIdx.x;
    const int b    = bc / CC;
    const int c    = bc % CC;
    const int tid  = threadIdx.x;
    const int lane = tid & 31;
    const int wid  = tid >> 5;

    __shared__ unsigned long long sk[16 * PITCH];  // padded runs; hist aliases
    __shared__ float4             sbox[16 * PD];
    __shared__ int                swarp[4];
    __shared__ int                s_count, s_cut;
    int* hist = (int*)sk;                          // 1024 ints = 4KB <= 4.2KB

    // ---- Scan-based collect from bitmask (no atomics)
    const unsigned* Cm = g_cmask + (size_t)bc * NW;
    unsigned mw[3];
    int cnt_t = 0;
#pragma unroll
    for (int j = 0; j < 3; j++) {
        int widx = tid * 3 + j;
        mw[j] = (widx < NW) ? Cm[widx] : 0u;
        cnt_t += __popc(mw[j]);
    }
    int inc = cnt_t;
#pragma unroll
    for (int off = 1; off < 32; off <<= 1) {
        int v = __shfl_up_sync(FULLM, inc, off);
        if (lane >= off) inc += v;
    }
    if (lane == 31) swarp[wid] = inc;
    __syncthreads();
    int wbase = 0;
#pragma unroll
    for (int k = 0; k < 4; k++) wbase += (k < wid) ? swarp[k] : 0;
    const int total    = swarp[0] + swarp[1] + swarp[2] + swarp[3];
    const int slotbase = wbase + inc - cnt_t;      // exclusive prefix

    int cnt = total;
    if (cnt >= KCAND && cnt <= 512) {
        // Fast path: positions first (ALU), then batched loads, then stores
        int myn[12];
        int idx = 0;
#pragma unroll
        for (int j = 0; j < 3; j++) {
            unsigned m = mw[j];
            const int nb = (tid * 3 + j) * 32;
            while (m) {
                int bit = __ffs(m) - 1;
                m &= m - 1;
                int n = nb + bit;
                if (idx < 12) {
                    myn[idx] = n;
                } else {  // statistically rare overflow: handle inline
                    float s = __ldg(labels + ((size_t)b * NN + n) * CC + c);
                    sk[PAD(slotbase + idx)] = pack_key(s, (unsigned)n);
                }
                idx++;
            }
        }
        const int kk = min(idx, 12);
        float sv[12];
#pragma unroll
        for (int q = 0; q < 12; q++)
            if (q < kk)
                sv[q] = __ldg(labels + ((size_t)b * NN + myn[q]) * CC + c);
#pragma unroll
        for (int q = 0; q < 12; q++)
            if (q < kk)
                sk[PAD(slotbase + q)] = pack_key(sv[q], (unsigned)myn[q]);
    } else {
        // Exact fallback (statistically never taken): histogram two-pass.
        for (int i = tid; i < 1024; i += 128) hist[i] = 0;
        if (tid == 0) s_count = 0;
        __syncthreads();

        const float*         Lcol = labels + (size_t)b * NN * CC + c;
        const unsigned char* Mb   = g_mask + (size_t)b * NN;

        for (int n = tid; n < NN; n += 128) {
            if (Mb[n]) {
                float s = Lcol[(size_t)n * CC];
                if (s > 0.0f)
                    atomicAdd(&hist[min((int)(s * 1024.0f), 1023)], 1);
            }
        }
        __syncthreads();
        if (tid == 0) {
            int cum = 0, cut = 0;
            for (int bin = 1023; bin >= 0; bin--) {
                cum += hist[bin];
                if (cum >= KCAND) { cut = bin; break; }
            }
            s_cut = cut;
        }
        __syncthreads();
        const int fcut = s_cut;
        __syncthreads();                      // hist reads done before reuse
        for (int n = tid; n < NN; n += 128) {
            if (Mb[n]) {
                float s = Lcol[(size_t)n * CC];
                if (s > 0.0f && min((int)(s * 1024.0f), 1023) >= fcut) {
                    int p = atomicAdd(&s_count, 1);
                    if (p < 512)
                        sk[PAD(p)] = pack_key(s, (unsigned)n);
                }
            }
        }
        __syncthreads();
        cnt = s_count;
    }
    __syncthreads();

    const int mn = min(cnt, 512);
    for (int i = mn + tid; i < 512; i += 128) sk[PAD(i)] = 0ULL;
    __syncthreads();

    // Sort active runs (strided across warps); lanes 0..PD-1 hold the run's
    // top-PD keys post-sort => issue box prefetch immediately (overlaps with
    // the next run's sort instead of stalling behind a barrier).
    const int nruns = (mn + 31) >> 5;
    for (int r = wid; r < nruns; r += 4) {
        unsigned long long k = sk[r * PITCH + lane];
        k = warpsort32_desc(k, lane);
        sk[r * PITCH + lane] = k;
        if (lane < PD && k) {
            unsigned n = 16383u - (unsigned)((k >> 9) & 0x3FFFu);
            sbox[r * PD + lane] = g_boxes[(size_t)b * NN + n];
        }
    }
    __syncthreads();

    // Warp 0: 16-way merge-pop fused with greedy NMS (exact top-200 order)
    if (wid == 0) {
        const int outbase = bc * MAXPC;
        int    head   = 0;
        int    kc     = 0;
        int    pops   = 0;
        const int maxpops = min(mn, KCAND);
        float4 mykept = make_float4(0.f, 0.f, 0.f, 0.f);

        while (pops < maxpops && kc < MAXPC) {
            unsigned long long hk = 0ULL;
            if (lane < 16 && head < 32) hk = sk[lane * PITCH + head];
            // two-stage REDUX argmax (keys unique; 0 = exhausted)
            unsigned hi  = (unsigned)(hk >> 32);
            unsigned mhi = __reduce_max_sync(FULLM, hi);
            unsigned lo  = (hi == mhi) ? (unsigned)hk : 0u;
            unsigned mlo = __reduce_max_sync(FULLM, lo);
            unsigned long long bk = ((unsigned long long)mhi << 32) | mlo;
            if (bk == 0ULL) break;
            unsigned bal = __ballot_sync(FULLM, hk == bk);
            int bl = __ffs(bal) - 1;
            int hd = __shfl_sync(FULLM, head, bl);
            if (lane == bl) head++;
            pops++;

            float s = __uint_as_float(mhi);
            if (s <= 0.5f) break;               // sorted: all later smaller
            float4 cb;
            if (hd < PD) {
                cb = sbox[bl * PD + hd];        // smem broadcast (common)
            } else {                            // rare: direct L1/L2 broadcast
                unsigned n = 16383u - (unsigned)((bk >> 9) & 0x3FFFu);
                cb = g_boxes[(size_t)b * NN + n];
            }

            bool ov = (lane < kc) && (iou_f(mykept, cb) > 0.5f);
            if (!__ballot_sync(FULLM, ov)) {
                if (lane == kc) mykept = cb;
                if (lane == 0) {
                    g_cls_scores[outbase + kc] = s;
                    g_cls_boxes[outbase + kc]  = cb;
                }
                kc++;
            }
        }
        if (lane < MAXPC && lane >= kc) {
            g_cls_scores[outbase + lane] = 0.0f;
            g_cls_boxes[outbase + lane]  = make_float4(0.f, 0.f, 0.f, 0.f);
        }
    }
}

// ---------------------------------------------------------------------------
// Kernel C (proven): rank-based per-batch top-20 of 420 entries.
// ---------------------------------------------------------------------------
__global__ __launch_bounds__(448) void merge_kernel(float* __restrict__ out) {
    const int b   = blockIdx.x;
    const int tid = threadIdx.x;

    __shared__ unsigned long long ks[CC * MAXPC];   // 420 keys

    float s = 0.0f;
    if (tid < CC * MAXPC) {
        s = g_cls_scores[b * CC * MAXPC + tid];
        ks[tid] = ((unsigned long long)__float_as_uint(s) << 16)
                  | (unsigned long long)(1023 - tid);
    }
    __syncthreads();

    if (tid < CC * MAXPC) {
        const unsigned long long myk = ks[tid];
        int rank = 0;
#pragma unroll 4
        for (int j = 0; j < CC * MAXPC; j++)
            rank += (ks[j] > myk);

        if (rank < MAXTOT) {
            float4 bx  = make_float4(0.f, 0.f, 0.f, 0.f);
            float  lab = 0.0f;
            if (s > 0.0f) {
                bx = g_cls_boxes[b * CC * MAXPC + tid];
                bx.x = fminf(fmaxf(bx.x, 0.0f), 1.0f);
                bx.y = fminf(fmaxf(bx.y, 0.0f), 1.0f);
                bx.z = fminf(fmaxf(bx.z, 0.0f), 1.0f);
                bx.w = fminf(fmaxf(bx.w, 0.0f), 1.0f);
                lab = (float)(tid / MAXPC);
            }
            float* ob = out + (size_t)b * MAXTOT * 4;
            float* ov = out + (size_t)BB * MAXTOT * 4 + (size_t)b * MAXTOT;
            float* ol = out + (size_t)BB * MAXTOT * 4 + (size_t)BB * MAXTOT
                            + (size_t)b * MAXTOT;
            ob[rank * 4 + 0] = bx.x;
            ob[rank * 4 + 1] = bx.y;
            ob[rank * 4 + 2] = bx.z;
            ob[rank * 4 + 3] = bx.w;
            ov[rank] = s;
            ol[rank] = lab;
        }
    }
}

// ---------------------------------------------------------------------------
extern "C" void kernel_launch(void* const* d_in, const int* in_sizes, int n_in,
                              void* d_out, int out_size) {
    const float* deltas  = (const float*)d_in[0];  // (64, 8732, 4)
    const float* labels  = (const float*)d_in[1];  // (64, 8732, 21)
    const float* anchors = (const float*)d_in[2];  // (8732, 4)
    float* out = (float*)d_out;

    decode_kernel<<<BB * BPB, DB>>>(deltas, labels, anchors);
    nms_kernel<<<BB * CC, 128>>>(labels);
    merge_kernel<<<BB, 448>>>(out);
}